// round 9
// baseline (speedup 1.0000x reference)
#include <cuda_runtime.h>
#include <cuda_fp16.h>

#define DIN 128
#define DH  128
#define MAXN 100000
#define MAXE 1600000
#define SLOTS 64          // fixed CSR slots per node (deg ~ Poisson(16); P(>64) ~ 1e-21)
#define NT16 6258         // row tiles, padded past 782*128 rows / 16

typedef unsigned long long ull;
typedef unsigned int uint32;

// ---- scratch (device globals: no allocation allowed) ----
__device__ int   g_cursor[MAXN];
__device__ int   g_csr[(size_t)MAXN * SLOTS];
// row-major fp16 features (for agg gathers)
__device__ unsigned short g_xh[(size_t)MAXN * DIN];
__device__ unsigned short g_hh[(size_t)MAXN * DH];
// fragment-layout fp16 matrices (for HMMA direct loads): [rowTile*8+kt][512B tiles]
__device__ unsigned short g_xfr[(size_t)NT16 * 2048];
__device__ unsigned short g_mfr[(size_t)NT16 * 2048];
__device__ unsigned short g_hfr[(size_t)NT16 * 2048];
// fragment-layout weights: [kt*8+nt2] tiles, kt 0..15, nt2 0..7
__device__ unsigned short g_W1f[128 * 256];
__device__ unsigned short g_W2f[128 * 256];

// ============================ prep: conversions + permutations ============================
// piece = one uint32 (2 halves, k even/odd) of a 512B fragment tile.
// inverse map: tile = p>>7, q = p&127, lane = q>>2, reg = q&3
//   row = rt*16 + (reg&1)*8 + (lane>>2),  k = kt*16 + (reg>>1)*8 + (lane&3)*2 + {0,1}
__global__ void k_prep(const float* __restrict__ x,
                       const float* __restrict__ w1l, const float* __restrict__ w1r,
                       const float* __restrict__ w2l, const float* __restrict__ w2r,
                       int n, int total4, int nfrp) {
    int i = blockIdx.x * blockDim.x + threadIdx.x;
    // row-major fp16 x (for agg gathers)
    if (i < total4) {
        float4 v = *(const float4*)(x + (size_t)i * 4);
        __half2 h0 = __floats2half2_rn(v.x, v.y);
        __half2 h1 = __floats2half2_rn(v.z, v.w);
        uint2 o; o.x = *(uint32*)&h0; o.y = *(uint32*)&h1;
        *(uint2*)((__half*)g_xh + (size_t)i * 4) = o;
    }
    // fragment-layout x
    if (i < nfrp) {
        int tile = i >> 7, q = i & 127;
        int lane = q >> 2, reg = q & 3;
        int rt = tile >> 3, kt = tile & 7;
        int row = rt * 16 + ((reg & 1) << 3) + (lane >> 2);
        int k   = kt * 16 + ((reg >> 1) << 3) + ((lane & 3) << 1);
        float v0 = 0.f, v1 = 0.f;
        if (row < n) { v0 = x[(size_t)row * 128 + k]; v1 = x[(size_t)row * 128 + k + 1]; }
        __half2 h = __floats2half2_rn(v0, v1);
        ((uint32*)g_xfr)[i] = *(uint32*)&h;
    }
    // fragment-layout weights: k = row of W (0..255), n = col
    if (i < 2 * 16384) {
        int wsel = i >> 14, j = i & 16383;
        int tile = j >> 7, q = j & 127;
        int lane = q >> 2, reg = q & 3;
        int kt = tile >> 3, nt2 = tile & 7;
        int k  = kt * 16 + ((reg & 1) << 3) + ((lane & 3) << 1);
        int nn = nt2 * 16 + ((reg >> 1) << 3) + (lane >> 2);
        const float* wl = wsel ? w2l : w1l;
        const float* wr = wsel ? w2r : w1r;
        float v0 = (k < 128)     ? wl[k * 128 + nn]           : wr[(k - 128) * 128 + nn];
        float v1 = (k + 1 < 128) ? wl[(k + 1) * 128 + nn]     : wr[(k + 1 - 128) * 128 + nn];
        __half2 h = __floats2half2_rn(v0, v1);
        ((uint32*)(wsel ? g_W2f : g_W1f))[j] = *(uint32*)&h;
    }
}

// ============================ slot-CSR scatter (2 edges/thread) ============================
__global__ void k_scatter(const int* __restrict__ row, const int* __restrict__ col, int e) {
    int i = (blockIdx.x * blockDim.x + threadIdx.x) * 2;
    if (i + 1 < e) {
        int2 r = *(const int2*)(row + i);
        int2 c = *(const int2*)(col + i);
        int p0 = atomicAdd(&g_cursor[c.x], 1);
        int p1 = atomicAdd(&g_cursor[c.y], 1);
        if (p0 < SLOTS) g_csr[(size_t)c.x * SLOTS + p0] = r.x;
        if (p1 < SLOTS) g_csr[(size_t)c.y * SLOTS + p1] = r.y;
    } else if (i < e) {
        int c = col[i];
        int pos = atomicAdd(&g_cursor[c], 1);
        if (pos < SLOTS) g_csr[(size_t)c * SLOTS + pos] = row[i];
    }
}

// ============================ mean aggregation -> fragment layout ============================
// one warp per node; gather identical to R8; epilogue scatters the mean row's
// 4B pieces into the fragment tiles (lanes 0..15 each own kt=(lane)>>1, k8=lane&1).
__global__ void k_agg_h(const __half* __restrict__ feat, int n) {
    int w = (blockIdx.x * blockDim.x + threadIdx.x) >> 5;
    int lane = threadIdx.x & 31;
    if (w >= n) return;
    int deg = g_cursor[w];
    if (deg > SLOTS) deg = SLOTS;
    const int* lst = g_csr + (size_t)w * SLOTS;
    int half = lane >> 4;
    int colb = (lane & 15) * 8;

    float acc[8];
    #pragma unroll
    for (int j = 0; j < 8; j++) acc[j] = 0.f;

    int rounds = (deg + 1) >> 1;
    int i = 0;
    for (; i + 2 <= rounds; i += 2) {
        int e0 = 2 * i + half;
        int e1 = 2 * (i + 1) + half;
        uint4 v0 = make_uint4(0, 0, 0, 0), v1 = make_uint4(0, 0, 0, 0);
        if (e0 < deg) { int s = lst[e0]; v0 = *(const uint4*)(feat + (size_t)s * DIN + colb); }
        if (e1 < deg) { int s = lst[e1]; v1 = *(const uint4*)(feat + (size_t)s * DIN + colb); }
        float2 f;
        f = __half22float2(*(__half2*)&v0.x); acc[0] += f.x; acc[1] += f.y;
        f = __half22float2(*(__half2*)&v0.y); acc[2] += f.x; acc[3] += f.y;
        f = __half22float2(*(__half2*)&v0.z); acc[4] += f.x; acc[5] += f.y;
        f = __half22float2(*(__half2*)&v0.w); acc[6] += f.x; acc[7] += f.y;
        f = __half22float2(*(__half2*)&v1.x); acc[0] += f.x; acc[1] += f.y;
        f = __half22float2(*(__half2*)&v1.y); acc[2] += f.x; acc[3] += f.y;
        f = __half22float2(*(__half2*)&v1.z); acc[4] += f.x; acc[5] += f.y;
        f = __half22float2(*(__half2*)&v1.w); acc[6] += f.x; acc[7] += f.y;
    }
    for (; i < rounds; ++i) {
        int e0 = 2 * i + half;
        uint4 v0 = make_uint4(0, 0, 0, 0);
        if (e0 < deg) { int s = lst[e0]; v0 = *(const uint4*)(feat + (size_t)s * DIN + colb); }
        float2 f;
        f = __half22float2(*(__half2*)&v0.x); acc[0] += f.x; acc[1] += f.y;
        f = __half22float2(*(__half2*)&v0.y); acc[2] += f.x; acc[3] += f.y;
        f = __half22float2(*(__half2*)&v0.z); acc[4] += f.x; acc[5] += f.y;
        f = __half22float2(*(__half2*)&v0.w); acc[6] += f.x; acc[7] += f.y;
    }
    #pragma unroll
    for (int j = 0; j < 8; j++)
        acc[j] += __shfl_xor_sync(0xffffffffu, acc[j], 16);

    if (half == 0) {
        float inv = 1.0f / fmaxf((float)deg, 1.0f);
        int rt = w >> 4, r8 = (w >> 3) & 1, r3 = w & 7;
        int kt = (lane & 15) >> 1, k8 = lane & 1;
        int reg = r8 + 2 * k8;
        uint32* dst = (uint32*)g_mfr + ((size_t)rt * 8 + kt) * 128;
        #pragma unroll
        for (int t = 0; t < 4; t++) {
            __half2 h = __floats2half2_rn(acc[2 * t] * inv, acc[2 * t + 1] * inv);
            dst[(r3 * 4 + t) * 4 + reg] = *(uint32*)&h;
        }
    }
}

// ============================ fragment-direct HMMA linear ============================
// out[m,:] = relu( [mean|feat] @ W + bias ). 256 threads, 8 warps, warp = 16 rows x 128 N.
// No smem, no barriers: A and B read as ready-made mma fragments (LDG.128).

__device__ __forceinline__ void mma16816(float* c, uint32 a0, uint32 a1, uint32 a2, uint32 a3,
                                         uint32 b0, uint32 b1) {
    asm volatile("mma.sync.aligned.m16n8k16.row.col.f32.f16.f16.f32 "
                 "{%0,%1,%2,%3}, {%4,%5,%6,%7}, {%8,%9}, {%0,%1,%2,%3};"
                 : "+f"(c[0]), "+f"(c[1]), "+f"(c[2]), "+f"(c[3])
                 : "r"(a0), "r"(a1), "r"(a2), "r"(a3), "r"(b0), "r"(b1));
}

template <int HALF_OUT>
__global__ void __launch_bounds__(256) k_gemm(
    const uint4* __restrict__ Amf, const uint4* __restrict__ Axf,
    const uint4* __restrict__ Wf, const float* __restrict__ bias,
    float* __restrict__ outf, __half* __restrict__ outh_rm,
    uint4* __restrict__ outh_fr, int n)
{
    int tid = (int)threadIdx.x;
    int lane = tid & 31;
    int warp = tid >> 5;                 // 0..7
    int bm = blockIdx.x * 128;
    int rt = (bm >> 4) + warp;           // this warp's row tile

    float acc[16][4];
    #pragma unroll
    for (int j = 0; j < 16; j++)
        #pragma unroll
        for (int q = 0; q < 4; q++) acc[j][q] = 0.f;

    #pragma unroll
    for (int kt = 0; kt < 16; kt++) {
        uint4 a = (kt < 8) ? Amf[((size_t)rt * 8 + kt) * 32 + lane]
                           : Axf[((size_t)rt * 8 + (kt - 8)) * 32 + lane];
        #pragma unroll
        for (int nt2 = 0; nt2 < 8; nt2++) {
            uint4 b = Wf[(kt * 8 + nt2) * 32 + lane];
            mma16816(acc[nt2 * 2],     a.x, a.y, a.z, a.w, b.x, b.y);
            mma16816(acc[nt2 * 2 + 1], a.x, a.y, a.z, a.w, b.z, b.w);
        }
    }

    // ---- epilogue: bias + relu ----
    int r0 = bm + warp * 16 + (lane >> 2);
    int r1 = r0 + 8;
    #pragma unroll
    for (int ktO = 0; ktO < 8; ktO++) {          // pairs of n-tiles
        uint32 frag[4];
        #pragma unroll
        for (int sub = 0; sub < 2; sub++) {
            int nt = ktO * 2 + sub;
            int col = nt * 8 + (lane & 3) * 2;
            float b0 = bias[col], b1 = bias[col + 1];
            float v00 = fmaxf(acc[nt][0] + b0, 0.f);
            float v01 = fmaxf(acc[nt][1] + b1, 0.f);
            float v10 = fmaxf(acc[nt][2] + b0, 0.f);
            float v11 = fmaxf(acc[nt][3] + b1, 0.f);
            if (HALF_OUT) {
                __half2 h0 = __floats2half2_rn(v00, v01);
                __half2 h1 = __floats2half2_rn(v10, v11);
                frag[sub * 2]     = *(uint32*)&h0;   // reg = r8 + 2*(nt&1)
                frag[sub * 2 + 1] = *(uint32*)&h1;
                if (r0 < n) *(__half2*)(outh_rm + (size_t)r0 * 128 + col) = h0;
                if (r1 < n) *(__half2*)(outh_rm + (size_t)r1 * 128 + col) = h1;
            } else {
                if (r0 < n) *(float2*)(outf + (size_t)r0 * 128 + col) = make_float2(v00, v01);
                if (r1 < n) *(float2*)(outf + (size_t)r1 * 128 + col) = make_float2(v10, v11);
            }
        }
        if (HALF_OUT && r0 < n) {
            outh_fr[((size_t)rt * 8 + ktO) * 32 + lane] = *(uint4*)frag;
        }
    }
}

// ============================ launch ============================

extern "C" void kernel_launch(void* const* d_in, const int* in_sizes, int n_in,
                              void* d_out, int out_size) {
    const float* x   = (const float*)d_in[0];
    const int*   ei  = (const int*)d_in[1];
    const float* w1l = (const float*)d_in[2];
    const float* b1l = (const float*)d_in[3];
    const float* w1r = (const float*)d_in[4];
    const float* w2l = (const float*)d_in[5];
    const float* b2l = (const float*)d_in[6];
    const float* w2r = (const float*)d_in[7];
    float* out = (float*)d_out;

    int n = in_sizes[0] / DIN;
    int e = in_sizes[1] / 2;
    if (n > MAXN) n = MAXN;
    if (e > MAXE) e = MAXE;
    const int* row = ei;       // edge_index[0] = source
    const int* col = ei + e;   // edge_index[1] = target

    void *pxh, *phh, *pxfr, *pmfr, *phfr, *pw1, *pw2, *pcur;
    cudaGetSymbolAddress(&pxh, g_xh);
    cudaGetSymbolAddress(&phh, g_hh);
    cudaGetSymbolAddress(&pxfr, g_xfr);
    cudaGetSymbolAddress(&pmfr, g_mfr);
    cudaGetSymbolAddress(&phfr, g_hfr);
    cudaGetSymbolAddress(&pw1, g_W1f);
    cudaGetSymbolAddress(&pw2, g_W2f);
    cudaGetSymbolAddress(&pcur, g_cursor);
    __half* xh = (__half*)pxh;
    __half* hh = (__half*)phh;

    // fork a side stream for the conversions (independent of CSR build)
    cudaStream_t side;
    cudaEvent_t evFork, evJoin;
    cudaStreamCreateWithFlags(&side, cudaStreamNonBlocking);
    cudaEventCreateWithFlags(&evFork, cudaEventDisableTiming);
    cudaEventCreateWithFlags(&evJoin, cudaEventDisableTiming);

    int total4 = (n * DIN) / 4;                  // 3.2M
    int ntr = (n + 15) >> 4;
    int nfrp = ntr * 1024;                       // fragment pieces for x (6.4M)
    int prepThreads = nfrp > total4 ? nfrp : total4;

    cudaEventRecord(evFork, 0);
    cudaStreamWaitEvent(side, evFork, 0);
    k_prep<<<(prepThreads + 255) / 256, 256, 0, side>>>(x, w1l, w1r, w2l, w2r, n, total4, nfrp);
    cudaEventRecord(evJoin, side);

    // main stream: slot-CSR build
    cudaMemsetAsync(pcur, 0, (size_t)n * sizeof(int), 0);
    int ethreads = (e + 1) / 2;
    k_scatter<<<(ethreads + 255) / 256, 256>>>(row, col, e);

    cudaStreamWaitEvent(0, evJoin, 0);

    int aggBlocks = (n * 32 + 255) / 256;
    int gemmBlocks = (n + 127) / 128;

    // layer 1: hh(_rm+_fr) = relu([mean(xh)|xh] @ W1 + b1)
    k_agg_h  <<<aggBlocks, 256>>>(xh, n);
    k_gemm<1><<<gemmBlocks, 256>>>((const uint4*)pmfr, (const uint4*)pxfr, (const uint4*)pw1,
                                   b1l, nullptr, hh, (uint4*)phfr, n);
    // layer 2: out = relu([mean(hh)|hh] @ W2 + b2) (fp32 row-major)
    k_agg_h  <<<aggBlocks, 256>>>(hh, n);
    k_gemm<0><<<gemmBlocks, 256>>>((const uint4*)pmfr, (const uint4*)phfr, (const uint4*)pw2,
                                   b2l, out, nullptr, nullptr, n);
}

// round 10
// speedup vs baseline: 1.1278x; 1.1278x over previous
#include <cuda_runtime.h>
#include <cuda_fp16.h>

#define DIN 128
#define DH  128
#define MAXN 100000
#define MAXE 1600000
#define SLOTS 64          // fixed CSR slots per node (deg ~ Poisson(16); P(>64) ~ 1e-21)

typedef unsigned long long ull;
typedef unsigned int uint32;

// ---- scratch (device globals: no allocation allowed) ----
__device__ int   g_cursor[MAXN];                        // per-node degree counter
__device__ int   g_csr[(size_t)MAXN * SLOTS];           // slot-CSR source lists
__device__ unsigned short g_xh[(size_t)MAXN * DIN];     // x in fp16
__device__ unsigned short g_meanh[(size_t)MAXN * DH];   // mean in fp16
__device__ unsigned short g_hh[(size_t)MAXN * DH];      // hidden in fp16
__device__ unsigned short g_pr[(size_t)MAXN * DH];      // partial (feat @ Wr) fp16
__device__ unsigned short g_W1[256 * 128];              // [w1l; w1r] fp16
__device__ unsigned short g_W2[256 * 128];              // [w2l; w2r] fp16

// ============================ prep: fp16 conversions ============================
__global__ void k_prep(const float* __restrict__ x,
                       const float* __restrict__ w1l, const float* __restrict__ w1r,
                       const float* __restrict__ w2l, const float* __restrict__ w2r,
                       int total4) {
    int i = blockIdx.x * blockDim.x + threadIdx.x;
    if (i < total4) {
        float4 v = *(const float4*)(x + (size_t)i * 4);
        __half2 h0 = __floats2half2_rn(v.x, v.y);
        __half2 h1 = __floats2half2_rn(v.z, v.w);
        uint2 o; o.x = *(uint32*)&h0; o.y = *(uint32*)&h1;
        *(uint2*)((__half*)g_xh + (size_t)i * 4) = o;
    }
    if (i < 128 * 128) {
        ((__half*)g_W1)[i]             = __float2half_rn(w1l[i]);
        ((__half*)g_W1)[128 * 128 + i] = __float2half_rn(w1r[i]);
        ((__half*)g_W2)[i]             = __float2half_rn(w2l[i]);
        ((__half*)g_W2)[128 * 128 + i] = __float2half_rn(w2r[i]);
    }
}

// ============================ slot-CSR scatter (2 edges/thread) ============================
__global__ void k_scatter(const int* __restrict__ row, const int* __restrict__ col, int e) {
    int i = (blockIdx.x * blockDim.x + threadIdx.x) * 2;
    if (i + 1 < e) {
        int2 r = *(const int2*)(row + i);
        int2 c = *(const int2*)(col + i);
        int p0 = atomicAdd(&g_cursor[c.x], 1);
        int p1 = atomicAdd(&g_cursor[c.y], 1);
        if (p0 < SLOTS) g_csr[(size_t)c.x * SLOTS + p0] = r.x;
        if (p1 < SLOTS) g_csr[(size_t)c.y * SLOTS + p1] = r.y;
    } else if (i < e) {
        int c = col[i];
        int pos = atomicAdd(&g_cursor[c], 1);
        if (pos < SLOTS) g_csr[(size_t)c * SLOTS + pos] = row[i];
    }
}

// ============================ mean aggregation ============================
// one warp per target node; 16 lanes cover a 256B feature row (uint4 each),
// so each load round gathers TWO source rows (lane>>4 selects which).
__global__ void k_agg_h(const __half* __restrict__ feat, __half* __restrict__ mean, int n) {
    int w = (blockIdx.x * blockDim.x + threadIdx.x) >> 5;
    int lane = threadIdx.x & 31;
    if (w >= n) return;
    int deg = g_cursor[w];
    if (deg > SLOTS) deg = SLOTS;
    const int* lst = g_csr + (size_t)w * SLOTS;
    int half = lane >> 4;
    int colb = (lane & 15) * 8;

    float acc[8];
    #pragma unroll
    for (int j = 0; j < 8; j++) acc[j] = 0.f;

    int rounds = (deg + 1) >> 1;
    int i = 0;
    for (; i + 2 <= rounds; i += 2) {
        int e0 = 2 * i + half;
        int e1 = 2 * (i + 1) + half;
        uint4 v0 = make_uint4(0, 0, 0, 0), v1 = make_uint4(0, 0, 0, 0);
        if (e0 < deg) { int s = lst[e0]; v0 = *(const uint4*)(feat + (size_t)s * DIN + colb); }
        if (e1 < deg) { int s = lst[e1]; v1 = *(const uint4*)(feat + (size_t)s * DIN + colb); }
        float2 f;
        f = __half22float2(*(__half2*)&v0.x); acc[0] += f.x; acc[1] += f.y;
        f = __half22float2(*(__half2*)&v0.y); acc[2] += f.x; acc[3] += f.y;
        f = __half22float2(*(__half2*)&v0.z); acc[4] += f.x; acc[5] += f.y;
        f = __half22float2(*(__half2*)&v0.w); acc[6] += f.x; acc[7] += f.y;
        f = __half22float2(*(__half2*)&v1.x); acc[0] += f.x; acc[1] += f.y;
        f = __half22float2(*(__half2*)&v1.y); acc[2] += f.x; acc[3] += f.y;
        f = __half22float2(*(__half2*)&v1.z); acc[4] += f.x; acc[5] += f.y;
        f = __half22float2(*(__half2*)&v1.w); acc[6] += f.x; acc[7] += f.y;
    }
    for (; i < rounds; ++i) {
        int e0 = 2 * i + half;
        uint4 v0 = make_uint4(0, 0, 0, 0);
        if (e0 < deg) { int s = lst[e0]; v0 = *(const uint4*)(feat + (size_t)s * DIN + colb); }
        float2 f;
        f = __half22float2(*(__half2*)&v0.x); acc[0] += f.x; acc[1] += f.y;
        f = __half22float2(*(__half2*)&v0.y); acc[2] += f.x; acc[3] += f.y;
        f = __half22float2(*(__half2*)&v0.z); acc[4] += f.x; acc[5] += f.y;
        f = __half22float2(*(__half2*)&v0.w); acc[6] += f.x; acc[7] += f.y;
    }
    #pragma unroll
    for (int j = 0; j < 8; j++)
        acc[j] += __shfl_xor_sync(0xffffffffu, acc[j], 16);

    if (half == 0) {
        float inv = 1.0f / fmaxf((float)deg, 1.0f);
        __half2 h0 = __floats2half2_rn(acc[0] * inv, acc[1] * inv);
        __half2 h1 = __floats2half2_rn(acc[2] * inv, acc[3] * inv);
        __half2 h2 = __floats2half2_rn(acc[4] * inv, acc[5] * inv);
        __half2 h3 = __floats2half2_rn(acc[6] * inv, acc[7] * inv);
        uint4 o; o.x = *(uint32*)&h0; o.y = *(uint32*)&h1; o.z = *(uint32*)&h2; o.w = *(uint32*)&h3;
        *(uint4*)(mean + (size_t)w * DH + colb) = o;
    }
}

// ============================ HMMA half-linear (cp.async pipelined, K=128) ============================
// MODE 0 (R): outh = A @ W                      (partial, fp16, no bias/relu)
// MODE 1 (L): outh = relu(A @ W + part + bias)  (fp16)
// MODE 2 (L): outf = relu(A @ W + part + bias)  (fp32)
// 256 threads (8 warps), block tile 128M x 128N, BK=64 double-buffered via cp.async.
// Warp grid 2M x 4N; warp tile 64M x 32N.

__device__ __forceinline__ void ldmx4(uint32& r0, uint32& r1, uint32& r2, uint32& r3, const void* p) {
    uint32 a = (uint32)__cvta_generic_to_shared(p);
    asm volatile("ldmatrix.sync.aligned.m8n8.x4.shared.b16 {%0,%1,%2,%3}, [%4];"
                 : "=r"(r0), "=r"(r1), "=r"(r2), "=r"(r3) : "r"(a));
}
__device__ __forceinline__ void ldmx4t(uint32& r0, uint32& r1, uint32& r2, uint32& r3, const void* p) {
    uint32 a = (uint32)__cvta_generic_to_shared(p);
    asm volatile("ldmatrix.sync.aligned.m8n8.x4.trans.shared.b16 {%0,%1,%2,%3}, [%4];"
                 : "=r"(r0), "=r"(r1), "=r"(r2), "=r"(r3) : "r"(a));
}
__device__ __forceinline__ void mma16816(float* c, uint32 a0, uint32 a1, uint32 a2, uint32 a3,
                                         uint32 b0, uint32 b1) {
    asm volatile("mma.sync.aligned.m16n8k16.row.col.f32.f16.f16.f32 "
                 "{%0,%1,%2,%3}, {%4,%5,%6,%7}, {%8,%9}, {%0,%1,%2,%3};"
                 : "+f"(c[0]), "+f"(c[1]), "+f"(c[2]), "+f"(c[3])
                 : "r"(a0), "r"(a1), "r"(a2), "r"(a3), "r"(b0), "r"(b1));
}
__device__ __forceinline__ void cpasync16(void* smp, const void* gp, int srcsz) {
    uint32 a = (uint32)__cvta_generic_to_shared(smp);
    asm volatile("cp.async.cg.shared.global [%0], [%1], 16, %2;"
                 :: "r"(a), "l"(gp), "r"(srcsz));
}
#define CP_COMMIT() asm volatile("cp.async.commit_group;")
#define CP_WAIT(N)  asm volatile("cp.async.wait_group %0;" :: "n"(N))

#define AS_STAGE (128 * 72)
#define BS_STAGE (64 * 136)
#define SMEM_HALVES (2 * (AS_STAGE + BS_STAGE))

template <int MODE>
__global__ void __launch_bounds__(256) k_gemm(
    const __half* __restrict__ A, const __half* __restrict__ W,
    const float* __restrict__ bias, const __half* __restrict__ part,
    float* __restrict__ outf, __half* __restrict__ outh, int n)
{
    extern __shared__ __half sm[];
    __half (*As)[128][72] = (__half(*)[128][72])(sm);
    __half (*Bs)[64][136] = (__half(*)[64][136])(sm + 2 * AS_STAGE);

    int tid = (int)threadIdx.x;
    int lane = tid & 31;
    int warp = tid >> 5;            // 0..7
    int wm = (warp & 1) * 64;
    int wn = (warp >> 1) * 32;
    int bm = blockIdx.x * 128;

    // ---- issue both chunks up front (K=128 -> exactly 2 stages) ----
    #pragma unroll
    for (int c = 0; c < 2; c++) {
        int koff = c * 64;
        #pragma unroll
        for (int h = 0; h < 4; h++) {
            int idx = tid + h * 256;
            int r = idx >> 3, g = (idx & 7) * 8;
            int gr = bm + r;
            cpasync16(&As[c][r][g], A + (size_t)(gr < n ? gr : 0) * 128 + koff + g, gr < n ? 16 : 0);
        }
        #pragma unroll
        for (int h = 0; h < 4; h++) {
            int idx = tid + h * 256;
            int r = idx >> 4, g = (idx & 15) * 8;
            cpasync16(&Bs[c][r][g], W + (size_t)(c * 64 + r) * 128 + g, 16);
        }
        CP_COMMIT();
    }

    float acc[4][4][4];
    #pragma unroll
    for (int ms = 0; ms < 4; ms++)
        #pragma unroll
        for (int nf = 0; nf < 4; nf++)
            #pragma unroll
            for (int q = 0; q < 4; q++) acc[ms][nf][q] = 0.f;

    #pragma unroll
    for (int c = 0; c < 2; c++) {
        if (c == 0) { CP_WAIT(1); } else { CP_WAIT(0); }
        __syncthreads();
        #pragma unroll
        for (int ks = 0; ks < 4; ks++) {
            uint32 b[8];
            ldmx4t(b[0], b[1], b[2], b[3], &Bs[c][ks * 16 + (lane & 15)][wn + (lane >> 4) * 8]);
            ldmx4t(b[4], b[5], b[6], b[7], &Bs[c][ks * 16 + (lane & 15)][wn + 16 + (lane >> 4) * 8]);
            #pragma unroll
            for (int ms = 0; ms < 4; ms++) {
                uint32 a0, a1, a2, a3;
                ldmx4(a0, a1, a2, a3, &As[c][wm + ms * 16 + (lane & 15)][ks * 16 + (lane >> 4) * 8]);
                mma16816(acc[ms][0], a0, a1, a2, a3, b[0], b[1]);
                mma16816(acc[ms][1], a0, a1, a2, a3, b[2], b[3]);
                mma16816(acc[ms][2], a0, a1, a2, a3, b[4], b[5]);
                mma16816(acc[ms][3], a0, a1, a2, a3, b[6], b[7]);
            }
        }
    }

    // ---- epilogue ----
    #pragma unroll
    for (int ms = 0; ms < 4; ms++) {
        int r0 = bm + wm + ms * 16 + (lane >> 2);
        int r1 = r0 + 8;
        #pragma unroll
        for (int nf = 0; nf < 4; nf++) {
            int col = wn + nf * 8 + (lane & 3) * 2;
            float v00 = acc[ms][nf][0], v01 = acc[ms][nf][1];
            float v10 = acc[ms][nf][2], v11 = acc[ms][nf][3];
            if (MODE == 0) {
                if (r0 < n) { __half2 h = __floats2half2_rn(v00, v01); *(__half2*)(outh + (size_t)r0 * 128 + col) = h; }
                if (r1 < n) { __half2 h = __floats2half2_rn(v10, v11); *(__half2*)(outh + (size_t)r1 * 128 + col) = h; }
            } else {
                float b0 = bias[col], b1 = bias[col + 1];
                if (r0 < n) {
                    float2 p = __half22float2(*(const __half2*)(part + (size_t)r0 * 128 + col));
                    float o0 = fmaxf(v00 + p.x + b0, 0.f);
                    float o1 = fmaxf(v01 + p.y + b1, 0.f);
                    if (MODE == 1) { __half2 h = __floats2half2_rn(o0, o1); *(__half2*)(outh + (size_t)r0 * 128 + col) = h; }
                    else           { *(float2*)(outf + (size_t)r0 * 128 + col) = make_float2(o0, o1); }
                }
                if (r1 < n) {
                    float2 p = __half22float2(*(const __half2*)(part + (size_t)r1 * 128 + col));
                    float o0 = fmaxf(v10 + p.x + b0, 0.f);
                    float o1 = fmaxf(v11 + p.y + b1, 0.f);
                    if (MODE == 1) { __half2 h = __floats2half2_rn(o0, o1); *(__half2*)(outh + (size_t)r1 * 128 + col) = h; }
                    else           { *(float2*)(outf + (size_t)r1 * 128 + col) = make_float2(o0, o1); }
                }
            }
        }
    }
}

// ============================ launch ============================

extern "C" void kernel_launch(void* const* d_in, const int* in_sizes, int n_in,
                              void* d_out, int out_size) {
    const float* x   = (const float*)d_in[0];
    const int*   ei  = (const int*)d_in[1];
    const float* w1l = (const float*)d_in[2];
    const float* b1l = (const float*)d_in[3];
    const float* w1r = (const float*)d_in[4];
    const float* w2l = (const float*)d_in[5];
    const float* b2l = (const float*)d_in[6];
    const float* w2r = (const float*)d_in[7];
    float* out = (float*)d_out;

    int n = in_sizes[0] / DIN;
    int e = in_sizes[1] / 2;
    if (n > MAXN) n = MAXN;
    if (e > MAXE) e = MAXE;
    const int* row = ei;       // edge_index[0] = source
    const int* col = ei + e;   // edge_index[1] = target

    void *pxh, *pmh, *phh, *ppr, *pw1, *pw2, *pcur;
    cudaGetSymbolAddress(&pxh, g_xh);
    cudaGetSymbolAddress(&pmh, g_meanh);
    cudaGetSymbolAddress(&phh, g_hh);
    cudaGetSymbolAddress(&ppr, g_pr);
    cudaGetSymbolAddress(&pw1, g_W1);
    cudaGetSymbolAddress(&pw2, g_W2);
    cudaGetSymbolAddress(&pcur, g_cursor);
    __half* xh    = (__half*)pxh;
    __half* meanh = (__half*)pmh;
    __half* hh    = (__half*)phh;
    __half* pr    = (__half*)ppr;
    __half* W1l   = (__half*)pw1;
    __half* W1r   = (__half*)pw1 + 128 * 128;
    __half* W2l   = (__half*)pw2;
    __half* W2r   = (__half*)pw2 + 128 * 128;

    int smemBytes = SMEM_HALVES * 2;   // 71680
    cudaFuncSetAttribute(k_gemm<0>, cudaFuncAttributeMaxDynamicSharedMemorySize, smemBytes);
    cudaFuncSetAttribute(k_gemm<1>, cudaFuncAttributeMaxDynamicSharedMemorySize, smemBytes);
    cudaFuncSetAttribute(k_gemm<2>, cudaFuncAttributeMaxDynamicSharedMemorySize, smemBytes);

    // persistent side stream + events (created once; never destroyed mid-capture)
    cudaStream_t side;
    cudaEvent_t evFork, evPrep, evR1, evH, evR2;
    cudaStreamCreateWithFlags(&side, cudaStreamNonBlocking);
    cudaEventCreateWithFlags(&evFork, cudaEventDisableTiming);
    cudaEventCreateWithFlags(&evPrep, cudaEventDisableTiming);
    cudaEventCreateWithFlags(&evR1, cudaEventDisableTiming);
    cudaEventCreateWithFlags(&evH, cudaEventDisableTiming);
    cudaEventCreateWithFlags(&evR2, cudaEventDisableTiming);

    int total4 = (n * DIN) / 4;
    int aggBlocks = (n * 32 + 255) / 256;
    int gemmBlocks = (n + 127) / 128;

    // fork side stream
    cudaEventRecord(evFork, 0);
    cudaStreamWaitEvent(side, evFork, 0);

    // side: prep -> gemmR1 (xh @ W1r -> pr)
    k_prep<<<(total4 + 255) / 256, 256, 0, side>>>(x, w1l, w1r, w2l, w2r, total4);
    cudaEventRecord(evPrep, side);
    k_gemm<0><<<gemmBlocks, 256, smemBytes, side>>>(xh, W1r, nullptr, nullptr, nullptr, pr, n);
    cudaEventRecord(evR1, side);

    // main: CSR build, then agg1 (needs xh from prep + csr)
    cudaMemsetAsync(pcur, 0, (size_t)n * sizeof(int), 0);
    int ethreads = (e + 1) / 2;
    k_scatter<<<(ethreads + 255) / 256, 256>>>(row, col, e);
    cudaStreamWaitEvent(0, evPrep, 0);
    k_agg_h<<<aggBlocks, 256>>>(xh, meanh, n);          // concurrent with gemmR1

    // main: gemmL1 = relu(mean@W1l + pr + b1) -> hh (needs evR1)
    cudaStreamWaitEvent(0, evR1, 0);
    k_gemm<1><<<gemmBlocks, 256, smemBytes>>>(meanh, W1l, b1l, pr, nullptr, hh, n);
    cudaEventRecord(evH, 0);

    // layer 2: agg2(main) concurrent with gemmR2(side)
    k_agg_h<<<aggBlocks, 256>>>(hh, meanh, n);
    cudaStreamWaitEvent(side, evH, 0);
    k_gemm<0><<<gemmBlocks, 256, smemBytes, side>>>(hh, W2r, nullptr, nullptr, nullptr, pr, n);
    cudaEventRecord(evR2, side);

    // main: gemmL2 = relu(mean@W2l + pr + b2) -> out fp32
    cudaStreamWaitEvent(0, evR2, 0);
    k_gemm<2><<<gemmBlocks, 256, smemBytes>>>(meanh, W2l, b2l, pr, out, nullptr, n);
}

// round 11
// speedup vs baseline: 1.2561x; 1.1138x over previous
#include <cuda_runtime.h>
#include <cuda_fp16.h>

#define DIN 128
#define DH  128
#define MAXN 100000
#define MAXE 1600000
#define SLOTS 64          // fixed CSR slots per node (deg ~ Poisson(16); P(>64) ~ 1e-21)

typedef unsigned long long ull;
typedef unsigned int uint32;

// ---- scratch (device globals: no allocation allowed) ----
__device__ int   g_cursor[MAXN];                        // per-node degree counter
__device__ int   g_csr[(size_t)MAXN * SLOTS];           // slot-CSR source lists
__device__ unsigned short g_xh[(size_t)MAXN * DIN];     // x in fp16
__device__ unsigned short g_meanh[(size_t)MAXN * DH];   // mean in fp16
__device__ unsigned short g_hh[(size_t)MAXN * DH];      // hidden in fp16
__device__ unsigned short g_W1[256 * 128];              // [w1l; w1r] fp16
__device__ unsigned short g_W2[256 * 128];              // [w2l; w2r] fp16

// ============================ prep: fp16 conversions ============================
__global__ void k_prep(const float* __restrict__ x,
                       const float* __restrict__ w1l, const float* __restrict__ w1r,
                       const float* __restrict__ w2l, const float* __restrict__ w2r,
                       int total4) {
    int i = blockIdx.x * blockDim.x + threadIdx.x;
    if (i < total4) {
        float4 v = *(const float4*)(x + (size_t)i * 4);
        __half2 h0 = __floats2half2_rn(v.x, v.y);
        __half2 h1 = __floats2half2_rn(v.z, v.w);
        uint2 o; o.x = *(uint32*)&h0; o.y = *(uint32*)&h1;
        *(uint2*)((__half*)g_xh + (size_t)i * 4) = o;
    }
    if (i < 128 * 128) {
        ((__half*)g_W1)[i]             = __float2half_rn(w1l[i]);
        ((__half*)g_W1)[128 * 128 + i] = __float2half_rn(w1r[i]);
        ((__half*)g_W2)[i]             = __float2half_rn(w2l[i]);
        ((__half*)g_W2)[128 * 128 + i] = __float2half_rn(w2r[i]);
    }
}

// ============================ slot-CSR scatter (4 edges/thread) ============================
__global__ void k_scatter(const int* __restrict__ row, const int* __restrict__ col, int e) {
    int i = (blockIdx.x * blockDim.x + threadIdx.x) * 4;
    if (i + 3 < e) {
        int4 r = *(const int4*)(row + i);
        int4 c = *(const int4*)(col + i);
        int p0 = atomicAdd(&g_cursor[c.x], 1);
        int p1 = atomicAdd(&g_cursor[c.y], 1);
        int p2 = atomicAdd(&g_cursor[c.z], 1);
        int p3 = atomicAdd(&g_cursor[c.w], 1);
        if (p0 < SLOTS) g_csr[(size_t)c.x * SLOTS + p0] = r.x;
        if (p1 < SLOTS) g_csr[(size_t)c.y * SLOTS + p1] = r.y;
        if (p2 < SLOTS) g_csr[(size_t)c.z * SLOTS + p2] = r.z;
        if (p3 < SLOTS) g_csr[(size_t)c.w * SLOTS + p3] = r.w;
    } else {
        for (int j = i; j < e; j++) {
            int c = col[j];
            int pos = atomicAdd(&g_cursor[c], 1);
            if (pos < SLOTS) g_csr[(size_t)c * SLOTS + pos] = row[j];
        }
    }
}

// ============================ mean aggregation (HADD2-paired) ============================
// one warp per target node; 16 lanes cover a 256B feature row (uint4 each).
// Main loop: 4 edges/iter; each half-warp loads 2 edges and pairs them with HADD2
// before converting to fp32 (half the F2F/FADD work).
__global__ void k_agg_h(const __half* __restrict__ feat, __half* __restrict__ mean, int n) {
    int w = (blockIdx.x * blockDim.x + threadIdx.x) >> 5;
    int lane = threadIdx.x & 31;
    if (w >= n) return;
    int deg = g_cursor[w];
    if (deg > SLOTS) deg = SLOTS;
    const int* lst = g_csr + (size_t)w * SLOTS;
    int half = lane >> 4;            // 0 or 1
    int colb = (lane & 15) * 8;      // 8 halves = 16B per lane

    float acc[8];
    #pragma unroll
    for (int j = 0; j < 8; j++) acc[j] = 0.f;

    int deg4 = deg & ~3;
    for (int i = 0; i < deg4; i += 4) {
        int s0 = lst[i + 2 * half];
        int s1 = lst[i + 2 * half + 1];
        uint4 v0 = *(const uint4*)(feat + (size_t)s0 * DIN + colb);
        uint4 v1 = *(const uint4*)(feat + (size_t)s1 * DIN + colb);
        __half2 p0 = __hadd2(*(__half2*)&v0.x, *(__half2*)&v1.x);
        __half2 p1 = __hadd2(*(__half2*)&v0.y, *(__half2*)&v1.y);
        __half2 p2 = __hadd2(*(__half2*)&v0.z, *(__half2*)&v1.z);
        __half2 p3 = __hadd2(*(__half2*)&v0.w, *(__half2*)&v1.w);
        float2 f;
        f = __half22float2(p0); acc[0] += f.x; acc[1] += f.y;
        f = __half22float2(p1); acc[2] += f.x; acc[3] += f.y;
        f = __half22float2(p2); acc[4] += f.x; acc[5] += f.y;
        f = __half22float2(p3); acc[6] += f.x; acc[7] += f.y;
    }
    // tail: up to 3 edges, half-warps take alternating edges
    for (int i = deg4; i < deg; i += 2) {
        int e0 = i + half;
        if (e0 < deg) {
            int s = lst[e0];
            uint4 v = *(const uint4*)(feat + (size_t)s * DIN + colb);
            float2 f;
            f = __half22float2(*(__half2*)&v.x); acc[0] += f.x; acc[1] += f.y;
            f = __half22float2(*(__half2*)&v.y); acc[2] += f.x; acc[3] += f.y;
            f = __half22float2(*(__half2*)&v.z); acc[4] += f.x; acc[5] += f.y;
            f = __half22float2(*(__half2*)&v.w); acc[6] += f.x; acc[7] += f.y;
        }
    }
    // combine the two half-warps
    #pragma unroll
    for (int j = 0; j < 8; j++)
        acc[j] += __shfl_xor_sync(0xffffffffu, acc[j], 16);

    if (half == 0) {
        float inv = 1.0f / fmaxf((float)deg, 1.0f);
        __half2 h0 = __floats2half2_rn(acc[0] * inv, acc[1] * inv);
        __half2 h1 = __floats2half2_rn(acc[2] * inv, acc[3] * inv);
        __half2 h2 = __floats2half2_rn(acc[4] * inv, acc[5] * inv);
        __half2 h3 = __floats2half2_rn(acc[6] * inv, acc[7] * inv);
        uint4 o; o.x = *(uint32*)&h0; o.y = *(uint32*)&h1; o.z = *(uint32*)&h2; o.w = *(uint32*)&h3;
        *(uint4*)(mean + (size_t)w * DH + colb) = o;
    }
}

// ============================ HMMA fused linear (cp.async pipelined) ============================
// out[m,:] = relu( [mean|xin] @ [Wl;Wr] + bias ), K=256, N=128.
// 256 threads (8 warps), block tile 128M x 128N, BK=64 double-buffered via cp.async.
// Warp grid 2M x 4N; warp tile 64M x 32N.

__device__ __forceinline__ void ldmx4(uint32& r0, uint32& r1, uint32& r2, uint32& r3, const void* p) {
    uint32 a = (uint32)__cvta_generic_to_shared(p);
    asm volatile("ldmatrix.sync.aligned.m8n8.x4.shared.b16 {%0,%1,%2,%3}, [%4];"
                 : "=r"(r0), "=r"(r1), "=r"(r2), "=r"(r3) : "r"(a));
}
__device__ __forceinline__ void ldmx4t(uint32& r0, uint32& r1, uint32& r2, uint32& r3, const void* p) {
    uint32 a = (uint32)__cvta_generic_to_shared(p);
    asm volatile("ldmatrix.sync.aligned.m8n8.x4.trans.shared.b16 {%0,%1,%2,%3}, [%4];"
                 : "=r"(r0), "=r"(r1), "=r"(r2), "=r"(r3) : "r"(a));
}
__device__ __forceinline__ void mma16816(float* c, uint32 a0, uint32 a1, uint32 a2, uint32 a3,
                                         uint32 b0, uint32 b1) {
    asm volatile("mma.sync.aligned.m16n8k16.row.col.f32.f16.f16.f32 "
                 "{%0,%1,%2,%3}, {%4,%5,%6,%7}, {%8,%9}, {%0,%1,%2,%3};"
                 : "+f"(c[0]), "+f"(c[1]), "+f"(c[2]), "+f"(c[3])
                 : "r"(a0), "r"(a1), "r"(a2), "r"(a3), "r"(b0), "r"(b1));
}
__device__ __forceinline__ void cpasync16(void* smp, const void* gp, int srcsz) {
    uint32 a = (uint32)__cvta_generic_to_shared(smp);
    asm volatile("cp.async.cg.shared.global [%0], [%1], 16, %2;"
                 :: "r"(a), "l"(gp), "r"(srcsz));
}
#define CP_COMMIT() asm volatile("cp.async.commit_group;")
#define CP_WAIT(N)  asm volatile("cp.async.wait_group %0;" :: "n"(N))

#define AS_STAGE (128 * 72)
#define BS_STAGE (64 * 136)
#define SMEM_HALVES (2 * (AS_STAGE + BS_STAGE))

template <int HALF_OUT>
__global__ void __launch_bounds__(256) k_gemm(
    const __half* __restrict__ Am, const __half* __restrict__ Ax,
    const __half* __restrict__ W, const float* __restrict__ bias,
    float* __restrict__ outf, __half* __restrict__ outh, int n)
{
    extern __shared__ __half sm[];
    __half (*As)[128][72] = (__half(*)[128][72])(sm);
    __half (*Bs)[64][136] = (__half(*)[64][136])(sm + 2 * AS_STAGE);

    int tid = (int)threadIdx.x;
    int lane = tid & 31;
    int warp = tid >> 5;            // 0..7
    int wm = (warp & 1) * 64;       // 2 M positions
    int wn = (warp >> 1) * 32;      // 4 N positions, 32 cols each
    int bm = blockIdx.x * 128;

    // ---- issue chunk 0 ----
    {
        #pragma unroll
        for (int h = 0; h < 4; h++) {
            int idx = tid + h * 256;      // 0..1023
            int r = idx >> 3, g = (idx & 7) * 8;
            int gr = bm + r;
            cpasync16(&As[0][r][g], Am + (size_t)(gr < n ? gr : 0) * 128 + g, gr < n ? 16 : 0);
        }
        #pragma unroll
        for (int h = 0; h < 4; h++) {
            int idx = tid + h * 256;
            int r = idx >> 4, g = (idx & 15) * 8;
            cpasync16(&Bs[0][r][g], W + (size_t)r * 128 + g, 16);
        }
        CP_COMMIT();
    }

    float acc[4][4][4];
    #pragma unroll
    for (int ms = 0; ms < 4; ms++)
        #pragma unroll
        for (int nf = 0; nf < 4; nf++)
            #pragma unroll
            for (int q = 0; q < 4; q++) acc[ms][nf][q] = 0.f;

    #pragma unroll
    for (int c = 0; c < 4; c++) {
        // issue chunk c+1 into the other buffer
        if (c + 1 < 4) {
            int cn = c + 1;
            const __half* src = (cn < 2) ? Am : Ax;
            int koff = (cn & 1) * 64;
            int buf = cn & 1;
            #pragma unroll
            for (int h = 0; h < 4; h++) {
                int idx = tid + h * 256;
                int r = idx >> 3, g = (idx & 7) * 8;
                int gr = bm + r;
                cpasync16(&As[buf][r][g], src + (size_t)(gr < n ? gr : 0) * 128 + koff + g, gr < n ? 16 : 0);
            }
            #pragma unroll
            for (int h = 0; h < 4; h++) {
                int idx = tid + h * 256;
                int r = idx >> 4, g = (idx & 15) * 8;
                cpasync16(&Bs[buf][r][g], W + (size_t)(cn * 64 + r) * 128 + g, 16);
            }
            CP_COMMIT();
            CP_WAIT(1);   // chunk c complete (chunk c+1 may still be in flight)
        } else {
            CP_WAIT(0);
        }
        __syncthreads();

        int buf = c & 1;
        #pragma unroll
        for (int ks = 0; ks < 4; ks++) {
            uint32 b[8];
            ldmx4t(b[0], b[1], b[2], b[3], &Bs[buf][ks * 16 + (lane & 15)][wn + (lane >> 4) * 8]);
            ldmx4t(b[4], b[5], b[6], b[7], &Bs[buf][ks * 16 + (lane & 15)][wn + 16 + (lane >> 4) * 8]);
            #pragma unroll
            for (int ms = 0; ms < 4; ms++) {
                uint32 a0, a1, a2, a3;
                ldmx4(a0, a1, a2, a3, &As[buf][wm + ms * 16 + (lane & 15)][ks * 16 + (lane >> 4) * 8]);
                mma16816(acc[ms][0], a0, a1, a2, a3, b[0], b[1]);
                mma16816(acc[ms][1], a0, a1, a2, a3, b[2], b[3]);
                mma16816(acc[ms][2], a0, a1, a2, a3, b[4], b[5]);
                mma16816(acc[ms][3], a0, a1, a2, a3, b[6], b[7]);
            }
        }
        __syncthreads();   // protect buf before chunk c+2 is issued into it
    }

    // ---- epilogue: bias + relu ----
    #pragma unroll
    for (int ms = 0; ms < 4; ms++) {
        int r0 = bm + wm + ms * 16 + (lane >> 2);
        int r1 = r0 + 8;
        #pragma unroll
        for (int nf = 0; nf < 4; nf++) {
            int col = wn + nf * 8 + (lane & 3) * 2;
            float b0 = bias[col], b1 = bias[col + 1];
            float v00 = fmaxf(acc[ms][nf][0] + b0, 0.f);
            float v01 = fmaxf(acc[ms][nf][1] + b1, 0.f);
            float v10 = fmaxf(acc[ms][nf][2] + b0, 0.f);
            float v11 = fmaxf(acc[ms][nf][3] + b1, 0.f);
            if (HALF_OUT) {
                if (r0 < n) { __half2 h = __floats2half2_rn(v00, v01); *(__half2*)(outh + (size_t)r0 * 128 + col) = h; }
                if (r1 < n) { __half2 h = __floats2half2_rn(v10, v11); *(__half2*)(outh + (size_t)r1 * 128 + col) = h; }
            } else {
                if (r0 < n) { *(float2*)(outf + (size_t)r0 * 128 + col) = make_float2(v00, v01); }
                if (r1 < n) { *(float2*)(outf + (size_t)r1 * 128 + col) = make_float2(v10, v11); }
            }
        }
    }
}

// ============================ launch ============================

extern "C" void kernel_launch(void* const* d_in, const int* in_sizes, int n_in,
                              void* d_out, int out_size) {
    const float* x   = (const float*)d_in[0];
    const int*   ei  = (const int*)d_in[1];
    const float* w1l = (const float*)d_in[2];
    const float* b1l = (const float*)d_in[3];
    const float* w1r = (const float*)d_in[4];
    const float* w2l = (const float*)d_in[5];
    const float* b2l = (const float*)d_in[6];
    const float* w2r = (const float*)d_in[7];
    float* out = (float*)d_out;

    int n = in_sizes[0] / DIN;
    int e = in_sizes[1] / 2;
    if (n > MAXN) n = MAXN;
    if (e > MAXE) e = MAXE;
    const int* row = ei;       // edge_index[0] = source
    const int* col = ei + e;   // edge_index[1] = target

    void *pxh, *pmh, *phh, *pw1, *pw2, *pcur;
    cudaGetSymbolAddress(&pxh, g_xh);
    cudaGetSymbolAddress(&pmh, g_meanh);
    cudaGetSymbolAddress(&phh, g_hh);
    cudaGetSymbolAddress(&pw1, g_W1);
    cudaGetSymbolAddress(&pw2, g_W2);
    cudaGetSymbolAddress(&pcur, g_cursor);
    __half* xh    = (__half*)pxh;
    __half* meanh = (__half*)pmh;
    __half* hh    = (__half*)phh;
    __half* W1    = (__half*)pw1;
    __half* W2    = (__half*)pw2;

    int smemBytes = SMEM_HALVES * 2;   // 71680
    cudaFuncSetAttribute(k_gemm<1>, cudaFuncAttributeMaxDynamicSharedMemorySize, smemBytes);
    cudaFuncSetAttribute(k_gemm<0>, cudaFuncAttributeMaxDynamicSharedMemorySize, smemBytes);

    // fork a side stream for the fp16 conversions (independent of CSR build).
    cudaStream_t side;
    cudaEvent_t evFork, evJoin;
    cudaStreamCreateWithFlags(&side, cudaStreamNonBlocking);
    cudaEventCreateWithFlags(&evFork, cudaEventDisableTiming);
    cudaEventCreateWithFlags(&evJoin, cudaEventDisableTiming);

    int total4 = (n * DIN) / 4;

    cudaEventRecord(evFork, 0);
    cudaStreamWaitEvent(side, evFork, 0);
    k_prep<<<(total4 + 255) / 256, 256, 0, side>>>(x, w1l, w1r, w2l, w2r, total4);
    cudaEventRecord(evJoin, side);

    // main stream: slot-CSR build
    cudaMemsetAsync(pcur, 0, (size_t)n * sizeof(int), 0);
    int ethreads = (e + 3) / 4;
    k_scatter<<<(ethreads + 255) / 256, 256>>>(row, col, e);

    // join: agg/gemm need xh + W1/W2
    cudaStreamWaitEvent(0, evJoin, 0);

    int aggBlocks = (n * 32 + 255) / 256;
    int gemmBlocks = (n + 127) / 128;

    // layer 1: hh = relu([mean(xh)|xh] @ W1 + b1)  (fp16 out)
    k_agg_h  <<<aggBlocks, 256>>>(xh, meanh, n);
    k_gemm<1><<<gemmBlocks, 256, smemBytes>>>(meanh, xh, W1, b1l, nullptr, hh, n);

    // layer 2: out = relu([mean(hh)|hh] @ W2 + b2) (fp32 out)
    k_agg_h  <<<aggBlocks, 256>>>(hh, meanh, n);
    k_gemm<0><<<gemmBlocks, 256, smemBytes>>>(meanh, hh, W2, b2l, out, nullptr, n);
}

// round 12
// speedup vs baseline: 1.2616x; 1.0044x over previous
#include <cuda_runtime.h>
#include <cuda_fp16.h>

#define DIN 128
#define DH  128
#define MAXN 100000
#define MAXE 1600000
#define SLOTS 64          // fixed CSR slots per node (deg ~ Poisson(16); P(>64) ~ 1e-21)

typedef unsigned long long ull;
typedef unsigned int uint32;

// ---- scratch (device globals: no allocation allowed) ----
__device__ int   g_cursor[MAXN];                        // per-node degree counter
__device__ int   g_csr[(size_t)MAXN * SLOTS];           // slot-CSR source lists
__device__ unsigned short g_xh[(size_t)MAXN * DIN];     // x in fp16
__device__ unsigned short g_meanh[(size_t)MAXN * DH];   // mean in fp16
__device__ unsigned short g_hh[(size_t)MAXN * DH];      // hidden in fp16
__device__ unsigned short g_W1[256 * 128];              // [w1l; w1r] fp16
__device__ unsigned short g_W2[256 * 128];              // [w2l; w2r] fp16

// ============================ prep: fp16 conversions ============================
__global__ void k_prep(const float* __restrict__ x,
                       const float* __restrict__ w1l, const float* __restrict__ w1r,
                       const float* __restrict__ w2l, const float* __restrict__ w2r,
                       int total4) {
    int i = blockIdx.x * blockDim.x + threadIdx.x;
    if (i < total4) {
        float4 v = *(const float4*)(x + (size_t)i * 4);
        __half2 h0 = __floats2half2_rn(v.x, v.y);
        __half2 h1 = __floats2half2_rn(v.z, v.w);
        uint2 o; o.x = *(uint32*)&h0; o.y = *(uint32*)&h1;
        *(uint2*)((__half*)g_xh + (size_t)i * 4) = o;
    }
    if (i < 128 * 128) {
        ((__half*)g_W1)[i]             = __float2half_rn(w1l[i]);
        ((__half*)g_W1)[128 * 128 + i] = __float2half_rn(w1r[i]);
        ((__half*)g_W2)[i]             = __float2half_rn(w2l[i]);
        ((__half*)g_W2)[128 * 128 + i] = __float2half_rn(w2r[i]);
    }
}

// ============================ slot-CSR scatter (4 edges/thread) ============================
__global__ void k_scatter(const int* __restrict__ row, const int* __restrict__ col, int e) {
    int i = (blockIdx.x * blockDim.x + threadIdx.x) * 4;
    if (i + 3 < e) {
        int4 r = *(const int4*)(row + i);
        int4 c = *(const int4*)(col + i);
        int p0 = atomicAdd(&g_cursor[c.x], 1);
        int p1 = atomicAdd(&g_cursor[c.y], 1);
        int p2 = atomicAdd(&g_cursor[c.z], 1);
        int p3 = atomicAdd(&g_cursor[c.w], 1);
        if (p0 < SLOTS) g_csr[(size_t)c.x * SLOTS + p0] = r.x;
        if (p1 < SLOTS) g_csr[(size_t)c.y * SLOTS + p1] = r.y;
        if (p2 < SLOTS) g_csr[(size_t)c.z * SLOTS + p2] = r.z;
        if (p3 < SLOTS) g_csr[(size_t)c.w * SLOTS + p3] = r.w;
    } else {
        for (int j = i; j < e; j++) {
            int c = col[j];
            int pos = atomicAdd(&g_cursor[c], 1);
            if (pos < SLOTS) g_csr[(size_t)c * SLOTS + pos] = row[j];
        }
    }
}

// ============================ mean aggregation (HADD2-paired) ============================
__global__ void k_agg_h(const __half* __restrict__ feat, __half* __restrict__ mean, int n) {
    int w = (blockIdx.x * blockDim.x + threadIdx.x) >> 5;
    int lane = threadIdx.x & 31;
    if (w >= n) return;
    int deg = g_cursor[w];
    if (deg > SLOTS) deg = SLOTS;
    const int* lst = g_csr + (size_t)w * SLOTS;
    int half = lane >> 4;            // 0 or 1
    int colb = (lane & 15) * 8;      // 8 halves = 16B per lane

    float acc[8];
    #pragma unroll
    for (int j = 0; j < 8; j++) acc[j] = 0.f;

    int deg4 = deg & ~3;
    for (int i = 0; i < deg4; i += 4) {
        int s0 = lst[i + 2 * half];
        int s1 = lst[i + 2 * half + 1];
        uint4 v0 = *(const uint4*)(feat + (size_t)s0 * DIN + colb);
        uint4 v1 = *(const uint4*)(feat + (size_t)s1 * DIN + colb);
        __half2 p0 = __hadd2(*(__half2*)&v0.x, *(__half2*)&v1.x);
        __half2 p1 = __hadd2(*(__half2*)&v0.y, *(__half2*)&v1.y);
        __half2 p2 = __hadd2(*(__half2*)&v0.z, *(__half2*)&v1.z);
        __half2 p3 = __hadd2(*(__half2*)&v0.w, *(__half2*)&v1.w);
        float2 f;
        f = __half22float2(p0); acc[0] += f.x; acc[1] += f.y;
        f = __half22float2(p1); acc[2] += f.x; acc[3] += f.y;
        f = __half22float2(p2); acc[4] += f.x; acc[5] += f.y;
        f = __half22float2(p3); acc[6] += f.x; acc[7] += f.y;
    }
    for (int i = deg4; i < deg; i += 2) {
        int e0 = i + half;
        if (e0 < deg) {
            int s = lst[e0];
            uint4 v = *(const uint4*)(feat + (size_t)s * DIN + colb);
            float2 f;
            f = __half22float2(*(__half2*)&v.x); acc[0] += f.x; acc[1] += f.y;
            f = __half22float2(*(__half2*)&v.y); acc[2] += f.x; acc[3] += f.y;
            f = __half22float2(*(__half2*)&v.z); acc[4] += f.x; acc[5] += f.y;
            f = __half22float2(*(__half2*)&v.w); acc[6] += f.x; acc[7] += f.y;
        }
    }
    #pragma unroll
    for (int j = 0; j < 8; j++)
        acc[j] += __shfl_xor_sync(0xffffffffu, acc[j], 16);

    if (half == 0) {
        float inv = 1.0f / fmaxf((float)deg, 1.0f);
        __half2 h0 = __floats2half2_rn(acc[0] * inv, acc[1] * inv);
        __half2 h1 = __floats2half2_rn(acc[2] * inv, acc[3] * inv);
        __half2 h2 = __floats2half2_rn(acc[4] * inv, acc[5] * inv);
        __half2 h3 = __floats2half2_rn(acc[6] * inv, acc[7] * inv);
        uint4 o; o.x = *(uint32*)&h0; o.y = *(uint32*)&h1; o.z = *(uint32*)&h2; o.w = *(uint32*)&h3;
        *(uint4*)(mean + (size_t)w * DH + colb) = o;
    }
}

// ============================ persistent HMMA fused linear ============================
// out[m,:] = relu( [mean|xin] @ [Wl;Wr] + bias ), K=256, N=128.
// Persistent: 296 CTAs (2/SM). B (=whole W, 4 chunks) resident in smem for the CTA's
// lifetime; A chunks double-buffered via cp.async, pipeline never drains across tiles.
// 256 threads, warp grid 2M x 4N, warp tile 64M x 32N.

__device__ __forceinline__ void ldmx4(uint32& r0, uint32& r1, uint32& r2, uint32& r3, const void* p) {
    uint32 a = (uint32)__cvta_generic_to_shared(p);
    asm volatile("ldmatrix.sync.aligned.m8n8.x4.shared.b16 {%0,%1,%2,%3}, [%4];"
                 : "=r"(r0), "=r"(r1), "=r"(r2), "=r"(r3) : "r"(a));
}
__device__ __forceinline__ void ldmx4t(uint32& r0, uint32& r1, uint32& r2, uint32& r3, const void* p) {
    uint32 a = (uint32)__cvta_generic_to_shared(p);
    asm volatile("ldmatrix.sync.aligned.m8n8.x4.trans.shared.b16 {%0,%1,%2,%3}, [%4];"
                 : "=r"(r0), "=r"(r1), "=r"(r2), "=r"(r3) : "r"(a));
}
__device__ __forceinline__ void mma16816(float* c, uint32 a0, uint32 a1, uint32 a2, uint32 a3,
                                         uint32 b0, uint32 b1) {
    asm volatile("mma.sync.aligned.m16n8k16.row.col.f32.f16.f16.f32 "
                 "{%0,%1,%2,%3}, {%4,%5,%6,%7}, {%8,%9}, {%0,%1,%2,%3};"
                 : "+f"(c[0]), "+f"(c[1]), "+f"(c[2]), "+f"(c[3])
                 : "r"(a0), "r"(a1), "r"(a2), "r"(a3), "r"(b0), "r"(b1));
}
__device__ __forceinline__ void cpasync16(void* smp, const void* gp, int srcsz) {
    uint32 a = (uint32)__cvta_generic_to_shared(smp);
    asm volatile("cp.async.cg.shared.global [%0], [%1], 16, %2;"
                 :: "r"(a), "l"(gp), "r"(srcsz));
}
#define CP_COMMIT() asm volatile("cp.async.commit_group;")
#define CP_WAIT(N)  asm volatile("cp.async.wait_group %0;" :: "n"(N))

#define AS_STAGE (128 * 72)
#define BS_STAGE (64 * 136)
#define SMEM_HALVES (2 * AS_STAGE + 4 * BS_STAGE)   // 53248 halves = 106496 B

template <int HALF_OUT>
__global__ void __launch_bounds__(256, 2) k_gemm(
    const __half* __restrict__ Am, const __half* __restrict__ Ax,
    const __half* __restrict__ W, const float* __restrict__ bias,
    float* __restrict__ outf, __half* __restrict__ outh, int n, int ntiles)
{
    extern __shared__ __half sm[];
    __half (*As)[128][72] = (__half(*)[128][72])(sm);
    __half (*Bs)[64][136] = (__half(*)[64][136])(sm + 2 * AS_STAGE);

    int tid = (int)threadIdx.x;
    int lane = tid & 31;
    int warp = tid >> 5;            // 0..7
    int wm = (warp & 1) * 64;
    int wn = (warp >> 1) * 32;

    // ---- load B (whole W) once: 4 chunks of 64x128 ----
    #pragma unroll
    for (int c = 0; c < 4; c++) {
        #pragma unroll
        for (int h = 0; h < 4; h++) {
            int idx = tid + h * 256;
            int r = idx >> 4, g = (idx & 15) * 8;
            cpasync16(&Bs[c][r][g], W + (size_t)(c * 64 + r) * 128 + g, 16);
        }
    }
    CP_COMMIT();

    int t = blockIdx.x;
    // issue A chunk 0 of first tile
    if (t < ntiles) {
        int bm = t * 128;
        #pragma unroll
        for (int h = 0; h < 4; h++) {
            int idx = tid + h * 256;
            int r = idx >> 3, g = (idx & 7) * 8;
            int gr = bm + r;
            cpasync16(&As[0][r][g], Am + (size_t)(gr < n ? gr : 0) * 128 + g, gr < n ? 16 : 0);
        }
    }
    CP_COMMIT();

    for (; t < ntiles; t += gridDim.x) {
        int bm = t * 128;
        int tn = t + gridDim.x;

        float acc[4][4][4];
        #pragma unroll
        for (int ms = 0; ms < 4; ms++)
            #pragma unroll
            for (int nf = 0; nf < 4; nf++)
                #pragma unroll
                for (int q = 0; q < 4; q++) acc[ms][nf][q] = 0.f;

        #pragma unroll
        for (int c = 0; c < 4; c++) {
            // prefetch the next chunk in the global stream
            if (c < 3) {
                int cn = c + 1;
                const __half* src = (cn < 2) ? Am : Ax;
                int koff = (cn & 1) * 64;
                int buf = cn & 1;
                #pragma unroll
                for (int h = 0; h < 4; h++) {
                    int idx = tid + h * 256;
                    int r = idx >> 3, g = (idx & 7) * 8;
                    int gr = bm + r;
                    cpasync16(&As[buf][r][g], src + (size_t)(gr < n ? gr : 0) * 128 + koff + g, gr < n ? 16 : 0);
                }
            } else if (tn < ntiles) {
                int bmn = tn * 128;
                #pragma unroll
                for (int h = 0; h < 4; h++) {
                    int idx = tid + h * 256;
                    int r = idx >> 3, g = (idx & 7) * 8;
                    int gr = bmn + r;
                    cpasync16(&As[0][r][g], Am + (size_t)(gr < n ? gr : 0) * 128 + g, gr < n ? 16 : 0);
                }
            }
            CP_COMMIT();                 // empty group OK; in-order completion
            CP_WAIT(1);                  // current chunk (and B) complete
            __syncthreads();

            int buf = c & 1;
            #pragma unroll
            for (int ks = 0; ks < 4; ks++) {
                uint32 b[8];
                ldmx4t(b[0], b[1], b[2], b[3], &Bs[c][ks * 16 + (lane & 15)][wn + (lane >> 4) * 8]);
                ldmx4t(b[4], b[5], b[6], b[7], &Bs[c][ks * 16 + (lane & 15)][wn + 16 + (lane >> 4) * 8]);
                #pragma unroll
                for (int ms = 0; ms < 4; ms++) {
                    uint32 a0, a1, a2, a3;
                    ldmx4(a0, a1, a2, a3, &As[buf][wm + ms * 16 + (lane & 15)][ks * 16 + (lane >> 4) * 8]);
                    mma16816(acc[ms][0], a0, a1, a2, a3, b[0], b[1]);
                    mma16816(acc[ms][1], a0, a1, a2, a3, b[2], b[3]);
                    mma16816(acc[ms][2], a0, a1, a2, a3, b[4], b[5]);
                    mma16816(acc[ms][3], a0, a1, a2, a3, b[6], b[7]);
                }
            }
            __syncthreads();             // protect buf before it is refilled
        }

        // ---- epilogue: bias + relu (registers/global only; overlaps in-flight A) ----
        #pragma unroll
        for (int ms = 0; ms < 4; ms++) {
            int r0 = bm + wm + ms * 16 + (lane >> 2);
            int r1 = r0 + 8;
            #pragma unroll
            for (int nf = 0; nf < 4; nf++) {
                int col = wn + nf * 8 + (lane & 3) * 2;
                float b0 = bias[col], b1 = bias[col + 1];
                float v00 = fmaxf(acc[ms][nf][0] + b0, 0.f);
                float v01 = fmaxf(acc[ms][nf][1] + b1, 0.f);
                float v10 = fmaxf(acc[ms][nf][2] + b0, 0.f);
                float v11 = fmaxf(acc[ms][nf][3] + b1, 0.f);
                if (HALF_OUT) {
                    if (r0 < n) { __half2 h = __floats2half2_rn(v00, v01); *(__half2*)(outh + (size_t)r0 * 128 + col) = h; }
                    if (r1 < n) { __half2 h = __floats2half2_rn(v10, v11); *(__half2*)(outh + (size_t)r1 * 128 + col) = h; }
                } else {
                    if (r0 < n) { *(float2*)(outf + (size_t)r0 * 128 + col) = make_float2(v00, v01); }
                    if (r1 < n) { *(float2*)(outf + (size_t)r1 * 128 + col) = make_float2(v10, v11); }
                }
            }
        }
    }
}

// ============================ launch ============================

extern "C" void kernel_launch(void* const* d_in, const int* in_sizes, int n_in,
                              void* d_out, int out_size) {
    const float* x   = (const float*)d_in[0];
    const int*   ei  = (const int*)d_in[1];
    const float* w1l = (const float*)d_in[2];
    const float* b1l = (const float*)d_in[3];
    const float* w1r = (const float*)d_in[4];
    const float* w2l = (const float*)d_in[5];
    const float* b2l = (const float*)d_in[6];
    const float* w2r = (const float*)d_in[7];
    float* out = (float*)d_out;

    int n = in_sizes[0] / DIN;
    int e = in_sizes[1] / 2;
    if (n > MAXN) n = MAXN;
    if (e > MAXE) e = MAXE;
    const int* row = ei;       // edge_index[0] = source
    const int* col = ei + e;   // edge_index[1] = target

    void *pxh, *pmh, *phh, *pw1, *pw2, *pcur;
    cudaGetSymbolAddress(&pxh, g_xh);
    cudaGetSymbolAddress(&pmh, g_meanh);
    cudaGetSymbolAddress(&phh, g_hh);
    cudaGetSymbolAddress(&pw1, g_W1);
    cudaGetSymbolAddress(&pw2, g_W2);
    cudaGetSymbolAddress(&pcur, g_cursor);
    __half* xh    = (__half*)pxh;
    __half* meanh = (__half*)pmh;
    __half* hh    = (__half*)phh;
    __half* W1    = (__half*)pw1;
    __half* W2    = (__half*)pw2;

    int smemBytes = SMEM_HALVES * 2;   // 106496
    cudaFuncSetAttribute(k_gemm<1>, cudaFuncAttributeMaxDynamicSharedMemorySize, smemBytes);
    cudaFuncSetAttribute(k_gemm<0>, cudaFuncAttributeMaxDynamicSharedMemorySize, smemBytes);

    // fork a side stream for the fp16 conversions (independent of CSR build).
    cudaStream_t side;
    cudaEvent_t evFork, evJoin;
    cudaStreamCreateWithFlags(&side, cudaStreamNonBlocking);
    cudaEventCreateWithFlags(&evFork, cudaEventDisableTiming);
    cudaEventCreateWithFlags(&evJoin, cudaEventDisableTiming);

    int total4 = (n * DIN) / 4;

    cudaEventRecord(evFork, 0);
    cudaStreamWaitEvent(side, evFork, 0);
    k_prep<<<(total4 + 255) / 256, 256, 0, side>>>(x, w1l, w1r, w2l, w2r, total4);
    cudaEventRecord(evJoin, side);

    // main stream: slot-CSR build
    cudaMemsetAsync(pcur, 0, (size_t)n * sizeof(int), 0);
    int ethreads = (e + 3) / 4;
    k_scatter<<<(ethreads + 255) / 256, 256>>>(row, col, e);

    // join: agg/gemm need xh + W1/W2
    cudaStreamWaitEvent(0, evJoin, 0);

    int aggBlocks = (n * 32 + 255) / 256;
    int ntiles = (n + 127) / 128;
    int gemmGrid = 296;              // 2 CTAs/SM persistent
    if (gemmGrid > ntiles) gemmGrid = ntiles;

    // layer 1: hh = relu([mean(xh)|xh] @ W1 + b1)  (fp16 out)
    k_agg_h  <<<aggBlocks, 256>>>(xh, meanh, n);
    k_gemm<1><<<gemmGrid, 256, smemBytes>>>(meanh, xh, W1, b1l, nullptr, hh, n, ntiles);

    // layer 2: out = relu([mean(hh)|hh] @ W2 + b2) (fp32 out)
    k_agg_h  <<<aggBlocks, 256>>>(hh, meanh, n);
    k_gemm<0><<<gemmGrid, 256, smemBytes>>>(meanh, hh, W2, b2l, out, nullptr, n, ntiles);
}